// round 9
// baseline (speedup 1.0000x reference)
#include <cuda_runtime.h>
#include <cuda_bf16.h>
#include <cstdint>

// NCEAverage: out[b,k] = exp(dot(memory[idx'[b,k]], x[b]) / T) / Z
// idx'[b,0] = y[b];  Z = mean(out_unnorm) * N
// B=256, K=4096, D=128, N=1e6, T=0.07
//
// Phase-partitioned gather, 8 phases: 512 blocks (single resident wave) each
// own one (b, 2048-k) range and deterministically bucket their 2048 row
// indices by row>>17 (slice ~67MB table / ~42MB unique-touched). The chip
// sweeps phases roughly together; slices are small enough that even +-1
// phase of drift keeps two slices L2-resident -> duplicate rows hit L2.
// idx read with __ldcs, out flushed with __stcs (no L2 pollution).
// Z: ticket + last-block fixed-order double reduce (deterministic).

#define B_SZ 256
#define K_SZ 4096
#define D_SZ 128
#define N_SZ 1000000
#define INV_T (1.0f / 0.07f)

#define TPB 256
#define WARPS 8
#define KRANGE 2048                    // k's per block
#define NBLK (B_SZ * K_SZ / KRANGE)    // 512 blocks = one resident wave
#define EPT (KRANGE / TPB)             // 8 indices per thread
#define PHASE_SHIFT 17                 // 8 phases of <=131072 rows (~67MB)
#define NPH 8

__device__ float        g_partials[NBLK];
__device__ float        g_scale;
__device__ unsigned int g_ticket;      // zero-init; last block resets

__global__ __launch_bounds__(TPB, 4)
void nce_scores_kernel(const float* __restrict__ x,
                       const int* __restrict__ y,
                       const int* __restrict__ idx,
                       const float* __restrict__ memory,
                       float* __restrict__ out) {
    __shared__ uint32_t           entries[KRANGE];   // (row<<11)|k_local
    __shared__ float              sout[KRANGE];      // staged scores
    __shared__ unsigned long long scanA[TPB];        // phases 0-3 counts
    __shared__ unsigned long long scanB[TPB];        // phases 4-7 counts
    __shared__ float              ssum[WARPS];
    __shared__ double             dsh[TPB];
    __shared__ bool               s_last;

    const int t     = threadIdx.x;
    const int lane  = t & 31;
    const int warp  = t >> 5;
    const int o     = lane & 7;        // octet within row
    const int r     = lane >> 3;       // which of 4 rows in a group
    const int b     = blockIdx.x >> 1;
    const int kbase = (blockIdx.x & 1) * KRANGE;

    // ---- 1. Load indices (streaming), count per phase ----
    const int* idx_b = idx + (size_t)b * K_SZ + kbase;
    uint32_t myrow[EPT];
    uint32_t cnt[NPH];
    #pragma unroll
    for (int p = 0; p < NPH; p++) cnt[p] = 0;
    #pragma unroll
    for (int j = 0; j < EPT; j++) {
        const int kl = j * TPB + t;
        const uint32_t row = (uint32_t)((kbase + kl == 0) ? y[b]
                                                          : __ldcs(&idx_b[kl]));
        myrow[j] = row;
        cnt[row >> PHASE_SHIFT] += 1u;
    }

    // ---- 2. Block-wide inclusive scan of 2x(4x16-bit) packed counts ----
    unsigned long long vA = (unsigned long long)cnt[0]
                          | ((unsigned long long)cnt[1] << 16)
                          | ((unsigned long long)cnt[2] << 32)
                          | ((unsigned long long)cnt[3] << 48);
    unsigned long long vB = (unsigned long long)cnt[4]
                          | ((unsigned long long)cnt[5] << 16)
                          | ((unsigned long long)cnt[6] << 32)
                          | ((unsigned long long)cnt[7] << 48);
    scanA[t] = vA;
    scanB[t] = vB;
    __syncthreads();
    #pragma unroll
    for (int off = 1; off < TPB; off <<= 1) {
        const unsigned long long aA = (t >= off) ? scanA[t - off] : 0ull;
        const unsigned long long aB = (t >= off) ? scanB[t - off] : 0ull;
        __syncthreads();
        scanA[t] += aA;
        scanB[t] += aB;
        __syncthreads();
    }
    const unsigned long long totA = scanA[TPB - 1];
    const unsigned long long totB = scanB[TPB - 1];
    const unsigned long long exA  = scanA[t] - vA;
    const unsigned long long exB  = scanB[t] - vB;

    uint32_t tc[NPH];
    #pragma unroll
    for (int p = 0; p < 4; p++) {
        tc[p]     = (uint32_t)(totA >> (16 * p)) & 0xffffu;
        tc[p + 4] = (uint32_t)(totB >> (16 * p)) & 0xffffu;
    }

    // per-phase write cursors for this thread (deterministic positions)
    uint32_t pos[NPH];
    {
        uint32_t base = 0;
        #pragma unroll
        for (int p = 0; p < NPH; p++) {
            const uint32_t ex = (p < 4)
                ? ((uint32_t)(exA >> (16 * p))       & 0xffffu)
                : ((uint32_t)(exB >> (16 * (p - 4))) & 0xffffu);
            pos[p] = base + ex;
            base += tc[p];
        }
    }

    // ---- 3. Deterministic scatter into phase buckets ----
    #pragma unroll
    for (int j = 0; j < EPT; j++) {
        const uint32_t row = myrow[j];
        const uint32_t p   = row >> PHASE_SHIFT;
        const uint32_t ent = (row << 11) | (uint32_t)(j * TPB + t);
        entries[pos[p]++] = ent;
    }
    __syncthreads();

    // ---- 4. Gather + dot + exp, phase by phase ----
    const float4* x4 = reinterpret_cast<const float4*>(x + b * D_SZ);
    const float4 xx0 = x4[0 * 8 + o];
    const float4 xx1 = x4[1 * 8 + o];
    const float4 xx2 = x4[2 * 8 + o];
    const float4 xx3 = x4[3 * 8 + o];

    float wsum = 0.0f;
    uint32_t lo = 0;
    #pragma unroll 1
    for (int p = 0; p < NPH; p++) {
        const uint32_t hi = lo + tc[p];
        for (uint32_t e0 = lo + (uint32_t)warp * 4u; e0 < hi; e0 += WARPS * 4u) {
            const uint32_t e = e0 + (uint32_t)r;
            const bool valid = (e < hi);
            float acc = 0.0f;
            uint32_t kl = 0;
            if (valid) {
                const uint32_t ent = entries[e];
                const uint32_t row = ent >> 11;
                kl = ent & 2047u;
                const float4* m4 = reinterpret_cast<const float4*>(memory + (size_t)row * D_SZ);
                const float4 w0 = m4[0 * 8 + o];
                const float4 w1 = m4[1 * 8 + o];
                const float4 w2 = m4[2 * 8 + o];
                const float4 w3 = m4[3 * 8 + o];
                acc  = w0.x * xx0.x + w0.y * xx0.y + w0.z * xx0.z + w0.w * xx0.w;
                acc += w1.x * xx1.x + w1.y * xx1.y + w1.z * xx1.z + w1.w * xx1.w;
                acc += w2.x * xx2.x + w2.y * xx2.y + w2.z * xx2.z + w2.w * xx2.w;
                acc += w3.x * xx3.x + w3.y * xx3.y + w3.z * xx3.z + w3.w * xx3.w;
            }
            // converge, then reduce the 8 lanes of each row (4 rows at once)
            acc += __shfl_xor_sync(0xffffffffu, acc, 1);
            acc += __shfl_xor_sync(0xffffffffu, acc, 2);
            acc += __shfl_xor_sync(0xffffffffu, acc, 4);
            if (o == 0 && valid) {
                const float s = __expf(acc * INV_T);
                sout[kl] = s;
                wsum += s;
            }
        }
        lo = hi;
    }

    // ---- 5. Coalesced streaming flush of staged scores ----
    __syncthreads();
    float4* ob4 = reinterpret_cast<float4*>(out + (size_t)b * K_SZ + kbase);
    const float4* so4 = reinterpret_cast<const float4*>(sout);
    #pragma unroll
    for (int i = 0; i < KRANGE / 4 / TPB; i++)      // 2 iterations
        __stcs(&ob4[t + i * TPB], so4[t + i * TPB]);

    // ---- 6. Block partial (fixed order) + ticket ----
    #pragma unroll
    for (int s = 16; s > 0; s >>= 1)
        wsum += __shfl_xor_sync(0xffffffffu, wsum, s);
    if (lane == 0) ssum[warp] = wsum;
    __syncthreads();
    if (t == 0) {
        float acc = 0.0f;
        #pragma unroll
        for (int w = 0; w < WARPS; w++) acc += ssum[w];
        g_partials[blockIdx.x] = acc;
        __threadfence();
        const unsigned int tk = atomicAdd(&g_ticket, 1u);
        s_last = (tk == NBLK - 1);
    }
    __syncthreads();

    // ---- 7. Last block: fixed-order double reduce of 512 partials ----
    if (s_last) {
        double acc = (double)g_partials[t] + (double)g_partials[t + TPB];
        dsh[t] = acc;
        __syncthreads();
        for (int s = TPB / 2; s > 0; s >>= 1) {
            if (t < s) dsh[t] += dsh[t + s];
            __syncthreads();
        }
        if (t == 0) {
            // Z = (sum / (B*K)) * N ; scale = 1/Z — double avoids fp32
            // overflow (sum ~ 1e31; sum*N would be inf in fp32).
            const double sum = dsh[0];
            g_scale = (float)(((double)B_SZ * (double)K_SZ) /
                              (sum * (double)N_SZ));
            g_ticket = 0u;             // reset for graph replay
            __threadfence();
        }
    }
}

// out: 262144 float4s -> 1024 blocks x 256 threads x 1 float4
__global__ __launch_bounds__(256)
void nce_norm_kernel(float* __restrict__ out) {
    const float s = g_scale;
    const int i = blockIdx.x * blockDim.x + threadIdx.x;
    float4* o = reinterpret_cast<float4*>(out);
    float4 v = o[i];
    v.x *= s; v.y *= s; v.z *= s; v.w *= s;
    o[i] = v;
}

extern "C" void kernel_launch(void* const* d_in, const int* in_sizes, int n_in,
                              void* d_out, int out_size) {
    const float* x      = (const float*)d_in[0];
    const int*   y      = (const int*)d_in[1];
    const int*   idx    = (const int*)d_in[2];
    const float* memory = (const float*)d_in[3];
    float* out = (float*)d_out;

    nce_scores_kernel<<<NBLK, TPB>>>(x, y, idx, memory, out);
    const int nvec4 = (B_SZ * K_SZ) / 4;   // 262144
    nce_norm_kernel<<<nvec4 / 256, 256>>>(out);
}

// round 10
// speedup vs baseline: 1.1108x; 1.1108x over previous
#include <cuda_runtime.h>
#include <cuda_bf16.h>
#include <cstdint>

// NCEAverage: out[b,k] = exp(dot(memory[idx'[b,k]], x[b]) / T) / Z
// idx'[b,0] = y[b];  Z = mean(out_unnorm) * N
// B=256, K=4096, D=128, N=1e6, T=0.07
//
// Phase-partitioned gather (4 phases — empirically optimal; 8 drifted):
// 512 blocks (single resident wave) each own one (b, 2048-k) range and
// deterministically bucket their 2048 row indices by row>>18; the chip
// sweeps phases roughly together so duplicate rows hit L2 instead of DRAM.
// Scores staged in SMEM, flushed with PLAIN stores so `out` (4MiB) stays
// L2-resident for the norm kernel's read (L2 hit vs DRAM miss).
// Z: ticket + last-block fixed-order double reduce (deterministic).

#define B_SZ 256
#define K_SZ 4096
#define D_SZ 128
#define N_SZ 1000000
#define INV_T (1.0f / 0.07f)

#define TPB 256
#define WARPS 8
#define KRANGE 2048                    // k's per block
#define NBLK (B_SZ * K_SZ / KRANGE)    // 512 blocks = one resident wave
#define EPT (KRANGE / TPB)             // 8 indices per thread
#define PHASE_SHIFT 18                 // 4 phases of <=262144 rows (~134MB)

__device__ float        g_partials[NBLK];
__device__ float        g_scale;
__device__ unsigned int g_ticket;      // zero-init; last block resets

__global__ __launch_bounds__(TPB, 4)
void nce_scores_kernel(const float* __restrict__ x,
                       const int* __restrict__ y,
                       const int* __restrict__ idx,
                       const float* __restrict__ memory,
                       float* __restrict__ out) {
    __shared__ uint32_t           entries[KRANGE];   // (row<<11)|k_local
    __shared__ float              sout[KRANGE];      // staged scores
    __shared__ unsigned long long scan[TPB];
    __shared__ float              ssum[WARPS];
    __shared__ double             dsh[TPB];
    __shared__ bool               s_last;

    const int t     = threadIdx.x;
    const int lane  = t & 31;
    const int warp  = t >> 5;
    const int o     = lane & 7;        // octet within row
    const int r     = lane >> 3;       // which of 4 rows in a group
    const int b     = blockIdx.x >> 1;
    const int kbase = (blockIdx.x & 1) * KRANGE;

    // ---- 1. Load indices, count per phase (thread-major canonical order) ----
    const int* idx_b = idx + (size_t)b * K_SZ + kbase;
    uint32_t myrow[EPT];
    uint32_t c0 = 0, c1 = 0, c2 = 0, c3 = 0;
    #pragma unroll
    for (int j = 0; j < EPT; j++) {
        const int kl = j * TPB + t;
        const uint32_t row = (uint32_t)((kbase + kl == 0) ? y[b] : idx_b[kl]);
        myrow[j] = row;
        const uint32_t p = row >> PHASE_SHIFT;
        c0 += (p == 0); c1 += (p == 1); c2 += (p == 2); c3 += (p == 3);
    }

    // ---- 2. Block-wide inclusive scan of 4x16-bit packed counts ----
    unsigned long long v = (unsigned long long)c0
                         | ((unsigned long long)c1 << 16)
                         | ((unsigned long long)c2 << 32)
                         | ((unsigned long long)c3 << 48);
    scan[t] = v;
    __syncthreads();
    #pragma unroll
    for (int off = 1; off < TPB; off <<= 1) {
        const unsigned long long add = (t >= off) ? scan[t - off] : 0ull;
        __syncthreads();
        scan[t] += add;
        __syncthreads();
    }
    const unsigned long long incl = scan[t];
    const unsigned long long tot  = scan[TPB - 1];
    const unsigned long long excl = incl - v;

    const uint32_t t0 = (uint32_t)(tot      ) & 0xffffu;
    const uint32_t t1 = (uint32_t)(tot >> 16) & 0xffffu;
    const uint32_t t2 = (uint32_t)(tot >> 32) & 0xffffu;
    const uint32_t t3 = (uint32_t)(tot >> 48) & 0xffffu;

    uint32_t pos0 =                ((uint32_t)(excl      ) & 0xffffu);
    uint32_t pos1 = t0           + ((uint32_t)(excl >> 16) & 0xffffu);
    uint32_t pos2 = t0 + t1      + ((uint32_t)(excl >> 32) & 0xffffu);
    uint32_t pos3 = t0 + t1 + t2 + ((uint32_t)(excl >> 48) & 0xffffu);

    // ---- 3. Deterministic scatter into phase buckets ----
    #pragma unroll
    for (int j = 0; j < EPT; j++) {
        const uint32_t row = myrow[j];
        const uint32_t p   = row >> PHASE_SHIFT;
        const uint32_t ent = (row << 11) | (uint32_t)(j * TPB + t);
        uint32_t pp;
        if      (p == 0) pp = pos0++;
        else if (p == 1) pp = pos1++;
        else if (p == 2) pp = pos2++;
        else             pp = pos3++;
        entries[pp] = ent;
    }
    __syncthreads();

    // ---- 4. Gather + dot + exp, phase by phase ----
    const float4* x4 = reinterpret_cast<const float4*>(x + b * D_SZ);
    const float4 xx0 = x4[0 * 8 + o];
    const float4 xx1 = x4[1 * 8 + o];
    const float4 xx2 = x4[2 * 8 + o];
    const float4 xx3 = x4[3 * 8 + o];

    const uint32_t tc[4] = { t0, t1, t2, t3 };
    float wsum = 0.0f;
    uint32_t lo = 0;
    #pragma unroll
    for (int p = 0; p < 4; p++) {
        const uint32_t hi = lo + tc[p];
        for (uint32_t e0 = lo + (uint32_t)warp * 4u; e0 < hi; e0 += WARPS * 4u) {
            const uint32_t e = e0 + (uint32_t)r;
            const bool valid = (e < hi);
            float acc = 0.0f;
            uint32_t kl = 0;
            if (valid) {
                const uint32_t ent = entries[e];
                const uint32_t row = ent >> 11;
                kl = ent & 2047u;
                const float4* m4 = reinterpret_cast<const float4*>(memory + (size_t)row * D_SZ);
                const float4 w0 = m4[0 * 8 + o];
                const float4 w1 = m4[1 * 8 + o];
                const float4 w2 = m4[2 * 8 + o];
                const float4 w3 = m4[3 * 8 + o];
                acc  = w0.x * xx0.x + w0.y * xx0.y + w0.z * xx0.z + w0.w * xx0.w;
                acc += w1.x * xx1.x + w1.y * xx1.y + w1.z * xx1.z + w1.w * xx1.w;
                acc += w2.x * xx2.x + w2.y * xx2.y + w2.z * xx2.z + w2.w * xx2.w;
                acc += w3.x * xx3.x + w3.y * xx3.y + w3.z * xx3.z + w3.w * xx3.w;
            }
            // converge, then reduce the 8 lanes of each row (4 rows at once)
            acc += __shfl_xor_sync(0xffffffffu, acc, 1);
            acc += __shfl_xor_sync(0xffffffffu, acc, 2);
            acc += __shfl_xor_sync(0xffffffffu, acc, 4);
            if (o == 0 && valid) {
                const float s = __expf(acc * INV_T);
                sout[kl] = s;
                wsum += s;
            }
        }
        lo = hi;
    }

    // ---- 5. Coalesced flush (plain stores: keep `out` L2-resident for norm) ----
    __syncthreads();
    float4* ob4 = reinterpret_cast<float4*>(out + (size_t)b * K_SZ + kbase);
    const float4* so4 = reinterpret_cast<const float4*>(sout);
    #pragma unroll
    for (int i = 0; i < KRANGE / 4 / TPB; i++)      // 2 iterations
        ob4[t + i * TPB] = so4[t + i * TPB];

    // ---- 6. Block partial (fixed order) + ticket ----
    #pragma unroll
    for (int s = 16; s > 0; s >>= 1)
        wsum += __shfl_xor_sync(0xffffffffu, wsum, s);
    if (lane == 0) ssum[warp] = wsum;
    __syncthreads();
    if (t == 0) {
        float acc = 0.0f;
        #pragma unroll
        for (int w = 0; w < WARPS; w++) acc += ssum[w];
        g_partials[blockIdx.x] = acc;
        __threadfence();
        const unsigned int tk = atomicAdd(&g_ticket, 1u);
        s_last = (tk == NBLK - 1);
    }
    __syncthreads();

    // ---- 7. Last block: fixed-order double reduce of 512 partials ----
    if (s_last) {
        double acc = (double)g_partials[t] + (double)g_partials[t + TPB];
        dsh[t] = acc;
        __syncthreads();
        for (int s = TPB / 2; s > 0; s >>= 1) {
            if (t < s) dsh[t] += dsh[t + s];
            __syncthreads();
        }
        if (t == 0) {
            // Z = (sum / (B*K)) * N ; scale = 1/Z — double avoids fp32
            // overflow (sum ~ 1e31; sum*N would be inf in fp32).
            const double sum = dsh[0];
            g_scale = (float)(((double)B_SZ * (double)K_SZ) /
                              (sum * (double)N_SZ));
            g_ticket = 0u;             // reset for graph replay
            __threadfence();
        }
    }
}

// out: 262144 float4s -> 1024 blocks x 256 threads x 1 float4.
// Reads hit L2 (scores flushed with plain stores); writes stream out.
__global__ __launch_bounds__(256)
void nce_norm_kernel(float* __restrict__ out) {
    const float s = g_scale;
    const int i = blockIdx.x * blockDim.x + threadIdx.x;
    float4* o = reinterpret_cast<float4*>(out);
    float4 v = o[i];
    v.x *= s; v.y *= s; v.z *= s; v.w *= s;
    __stcs(&o[i], v);
}

extern "C" void kernel_launch(void* const* d_in, const int* in_sizes, int n_in,
                              void* d_out, int out_size) {
    const float* x      = (const float*)d_in[0];
    const int*   y      = (const int*)d_in[1];
    const int*   idx    = (const int*)d_in[2];
    const float* memory = (const float*)d_in[3];
    float* out = (float*)d_out;

    nce_scores_kernel<<<NBLK, TPB>>>(x, y, idx, memory, out);
    const int nvec4 = (B_SZ * K_SZ) / 4;   // 262144
    nce_norm_kernel<<<nvec4 / 256, 256>>>(out);
}